// round 10
// baseline (speedup 1.0000x reference)
#include <cuda_runtime.h>
#include <math.h>

#define C_CH  4096
#define IMGSZ 64
#define NPM   4
#define OUT_N (C_CH * IMGSZ * IMGSZ)   // elements per multiplier index

typedef unsigned long long u64;

// Scratch: effective weights + running max (as monotone uint keys)
__device__ float        g_w[NPM * 9];
__device__ unsigned int g_maxbits[NPM];

__device__ __forceinline__ unsigned fkey(float f) {
    unsigned b = __float_as_uint(f);
    return (b & 0x80000000u) ? ~b : (b | 0x80000000u);
}
__device__ __forceinline__ float keyf(unsigned k) {
    return __uint_as_float((k & 0x80000000u) ? (k ^ 0x80000000u) : ~k);
}

// ---- packed f32x2 helpers (sm_103a; ptxas won't auto-fuse) ----
__device__ __forceinline__ u64 pack2(float lo, float hi) {
    u64 r;
    asm("mov.b64 %0, {%1, %2};" : "=l"(r) : "r"(__float_as_uint(lo)), "r"(__float_as_uint(hi)));
    return r;
}
__device__ __forceinline__ u64 dup2(float v) { return pack2(v, v); }
__device__ __forceinline__ void unpack2(u64 p, float& lo, float& hi) {
    unsigned a, b;
    asm("mov.b64 {%0, %1}, %2;" : "=r"(a), "=r"(b) : "l"(p));
    lo = __uint_as_float(a); hi = __uint_as_float(b);
}
__device__ __forceinline__ u64 mul2(u64 a, u64 b) {
    u64 r; asm("mul.rn.f32x2 %0, %1, %2;" : "=l"(r) : "l"(a), "l"(b)); return r;
}
__device__ __forceinline__ u64 fma2(u64 a, u64 b, u64 c) {
    u64 r; asm("fma.rn.f32x2 %0, %1, %2, %3;" : "=l"(r) : "l"(a), "l"(b), "l"(c)); return r;
}

// ---------------------------------------------------------------------------
// Kernel 0: build effective 3x3 kernels, reset max accumulators
// ---------------------------------------------------------------------------
__global__ void prep_kernel(const float* __restrict__ w, const float* __restrict__ wf) {
    int t = threadIdx.x;
    if (t < NPM * 9) {
        int n = t / 9;
        float wv = fminf(fmaxf(w[t], -1.f), 1.f);
        float f  = fminf(fmaxf(wf[n], 1.f), 255.f);
        g_w[t] = wv * f;
    }
    if (t < NPM) g_maxbits[t] = 0u;
}

// Load one image row segment cols [w0-1 .. w0+4] (zero-padded), duplicated
// into f32x2 broadcast pairs.
__device__ __forceinline__ void load_row_dup(const float* __restrict__ img, int r, int w0,
                                             bool hl, bool hr, u64 d[6]) {
    if ((unsigned)r < (unsigned)IMGSZ) {
        const float4 m = *reinterpret_cast<const float4*>(img + (r << 6) + w0);
        d[0] = dup2(hl ? img[(r << 6) + w0 - 1] : 0.f);
        d[1] = dup2(m.x); d[2] = dup2(m.y); d[3] = dup2(m.z); d[4] = dup2(m.w);
        d[5] = dup2(hr ? img[(r << 6) + w0 + 4] : 0.f);
    } else {
#pragma unroll
        for (int j = 0; j < 6; j++) d[j] = 0ull;
    }
}

// 9-tap packed conv for one output pixel, multiplier-pair p. Fixed tap order
// -> bit-exact across all variants.
__device__ __forceinline__ u64 conv9(const u64* wp, const u64 r0[6], const u64 r1[6],
                                     const u64 r2[6], int oc) {
    u64 a = mul2(wp[0], r0[oc]);
    a = fma2(wp[1], r0[oc + 1], a);
    a = fma2(wp[2], r0[oc + 2], a);
    a = fma2(wp[3], r1[oc],     a);
    a = fma2(wp[4], r1[oc + 1], a);
    a = fma2(wp[5], r1[oc + 2], a);
    a = fma2(wp[6], r2[oc],     a);
    a = fma2(wp[7], r2[oc + 1], a);
    a = fma2(wp[8], r2[oc + 2], a);
    return a;
}

// ---------------------------------------------------------------------------
// Kernel A: conv (4 kernels x all channels) + global max per multiplier index.
// One block per channel, 128 threads, 4-wide x 8-tall tile per thread.
// ---------------------------------------------------------------------------
__global__ void __launch_bounds__(128)
conv_max_kernel(const float* __restrict__ in) {
    int c = blockIdx.x;
    const float* img = in + c * (IMGSZ * IMGSZ);
    int tid = threadIdx.x;
    int tx = tid & 15, ty = tid >> 4;          // tx 0..15, ty 0..7
    int w0 = tx << 2, r0 = ty << 3;            // 4-wide, 8-tall
    bool hl = (tx != 0), hr = (tx != 15);

    u64 wp[2][9];
#pragma unroll
    for (int p = 0; p < 2; p++)
#pragma unroll
        for (int j = 0; j < 9; j++)
            wp[p][j] = pack2(g_w[(2 * p) * 9 + j], g_w[(2 * p + 1) * 9 + j]);

    u64 rw[3][6];
    load_row_dup(img, r0 - 1, w0, hl, hr, rw[0]);
    load_row_dup(img, r0,     w0, hl, hr, rw[1]);

    const float NEG_INF = __int_as_float(0xff800000);
    float mx[4] = {NEG_INF, NEG_INF, NEG_INF, NEG_INF};

#pragma unroll
    for (int orr = 0; orr < 8; orr++) {
        load_row_dup(img, r0 + orr + 1, w0, hl, hr, rw[2]);
#pragma unroll
        for (int p = 0; p < 2; p++) {
#pragma unroll
            for (int oc = 0; oc < 4; oc++) {
                u64 a = conv9(wp[p], rw[0], rw[1], rw[2], oc);
                float f0, f1; unpack2(a, f0, f1);
                mx[2 * p]     = fmaxf(mx[2 * p],     f0);
                mx[2 * p + 1] = fmaxf(mx[2 * p + 1], f1);
            }
        }
#pragma unroll
        for (int j = 0; j < 6; j++) { rw[0][j] = rw[1][j]; rw[1][j] = rw[2][j]; }
    }

#pragma unroll
    for (int n = 0; n < 4; n++) {
#pragma unroll
        for (int off = 16; off; off >>= 1)
            mx[n] = fmaxf(mx[n], __shfl_xor_sync(0xffffffffu, mx[n], off));
    }

    __shared__ float red[4][4];
    int wid = tid >> 5, lane = tid & 31;
    if (lane == 0) {
        red[wid][0] = mx[0]; red[wid][1] = mx[1];
        red[wid][2] = mx[2]; red[wid][3] = mx[3];
    }
    __syncthreads();
    if (tid < 4) {
        float m = red[0][tid];
#pragma unroll
        for (int wi = 1; wi < 4; wi++) m = fmaxf(m, red[wi][tid]);
        atomicMax(&g_maxbits[tid], fkey(m));
    }
}

// ---------------------------------------------------------------------------
// Kernel C: recompute conv, power-of-two renorm, add input, store.
// One block per channel, 128 threads, 4-wide x 8-tall tile per thread.
// ---------------------------------------------------------------------------
__global__ void __launch_bounds__(128)
conv_out_kernel(const float* __restrict__ in, float* __restrict__ out) {
    int c = blockIdx.x;
    const float* img = in + c * (IMGSZ * IMGSZ);
    int tid = threadIdx.x;
    int tx = tid & 15, ty = tid >> 4;
    int w0 = tx << 2, r0 = ty << 3;
    bool hl = (tx != 0), hr = (tx != 15);

    u64 wp[2][9];
#pragma unroll
    for (int p = 0; p < 2; p++)
#pragma unroll
        for (int j = 0; j < 9; j++)
            wp[p][j] = pack2(g_w[(2 * p) * 9 + j], g_w[(2 * p + 1) * 9 + j]);

    u64 scp[2];
    {
        float sc[4];
#pragma unroll
        for (int n = 0; n < 4; n++) {
            float m   = keyf(g_maxbits[n]);
            float div = m * 0.0078125f;   // /128
            float s = 1.f;
            if (div > 0.f) s = exp2f(-rintf(log2f(div)));   // round-half-even == jnp.round
            sc[n] = s;
        }
        scp[0] = pack2(sc[0], sc[1]);
        scp[1] = pack2(sc[2], sc[3]);
    }

    u64 rw[3][6];
    load_row_dup(img, r0 - 1, w0, hl, hr, rw[0]);
    load_row_dup(img, r0,     w0, hl, hr, rw[1]);

    float* outc = out + c * (IMGSZ * IMGSZ) + w0;

#pragma unroll
    for (int orr = 0; orr < 8; orr++) {
        load_row_dup(img, r0 + orr + 1, w0, hl, hr, rw[2]);
        int rowoff = (r0 + orr) << 6;
        float4 o0, o1, o2, o3;
#pragma unroll
        for (int oc = 0; oc < 4; oc++) {
            u64 a0 = conv9(wp[0], rw[0], rw[1], rw[2], oc);
            u64 r0p = fma2(a0, scp[0], rw[1][oc + 1]);   // input + conv*scale (n0,n1)
            float f0, f1; unpack2(r0p, f0, f1);
            ((float*)&o0)[oc] = f0;
            ((float*)&o1)[oc] = f1;

            u64 a1 = conv9(wp[1], rw[0], rw[1], rw[2], oc);
            u64 r1p = fma2(a1, scp[1], rw[1][oc + 1]);   // (n2,n3)
            float f2, f3; unpack2(r1p, f2, f3);
            ((float*)&o2)[oc] = f2;
            ((float*)&o3)[oc] = f3;
        }
        *reinterpret_cast<float4*>(outc + 0 * OUT_N + rowoff) = o0;
        *reinterpret_cast<float4*>(outc + 1 * OUT_N + rowoff) = o1;
        *reinterpret_cast<float4*>(outc + 2 * OUT_N + rowoff) = o2;
        *reinterpret_cast<float4*>(outc + 3 * OUT_N + rowoff) = o3;
#pragma unroll
        for (int j = 0; j < 6; j++) { rw[0][j] = rw[1][j]; rw[1][j] = rw[2][j]; }
    }
}

// ---------------------------------------------------------------------------
extern "C" void kernel_launch(void* const* d_in, const int* in_sizes, int n_in,
                              void* d_out, int out_size) {
    const float* input  = (const float*)d_in[0];   // [1,4096,64,64]
    const float* weight = (const float*)d_in[1];   // [4,9]
    const float* wf     = (const float*)d_in[2];   // [4,1]
    float* out = (float*)d_out;                    // [4,1,4096,64,64]

    prep_kernel<<<1, 64>>>(weight, wf);
    conv_max_kernel<<<C_CH, 128>>>(input);
    conv_out_kernel<<<C_CH, 128>>>(input, out);
}

// round 11
// speedup vs baseline: 1.2660x; 1.2660x over previous
#include <cuda_runtime.h>
#include <math.h>

#define C_CH  4096
#define IMGSZ 64
#define NPM   4
#define OUT_N (C_CH * IMGSZ * IMGSZ)   // elements per multiplier index

typedef unsigned long long u64;

// Scratch: effective weights + running max (as monotone uint keys)
__device__ float        g_w[NPM * 9];
__device__ unsigned int g_maxbits[NPM];

__device__ __forceinline__ unsigned fkey(float f) {
    unsigned b = __float_as_uint(f);
    return (b & 0x80000000u) ? ~b : (b | 0x80000000u);
}
__device__ __forceinline__ float keyf(unsigned k) {
    return __uint_as_float((k & 0x80000000u) ? (k ^ 0x80000000u) : ~k);
}

// ---- packed f32x2 helpers (sm_103a; ptxas won't auto-fuse) ----
__device__ __forceinline__ u64 pack2(float lo, float hi) {
    u64 r;
    asm("mov.b64 %0, {%1, %2};" : "=l"(r) : "r"(__float_as_uint(lo)), "r"(__float_as_uint(hi)));
    return r;
}
__device__ __forceinline__ u64 dup2(float v) { return pack2(v, v); }
__device__ __forceinline__ void unpack2(u64 p, float& lo, float& hi) {
    unsigned a, b;
    asm("mov.b64 {%0, %1}, %2;" : "=r"(a), "=r"(b) : "l"(p));
    lo = __uint_as_float(a); hi = __uint_as_float(b);
}
__device__ __forceinline__ u64 mul2(u64 a, u64 b) {
    u64 r; asm("mul.rn.f32x2 %0, %1, %2;" : "=l"(r) : "l"(a), "l"(b)); return r;
}
__device__ __forceinline__ u64 fma2(u64 a, u64 b, u64 c) {
    u64 r; asm("fma.rn.f32x2 %0, %1, %2, %3;" : "=l"(r) : "l"(a), "l"(b), "l"(c)); return r;
}

// ---------------------------------------------------------------------------
// Kernel 0: build effective 3x3 kernels, reset max accumulators
// ---------------------------------------------------------------------------
__global__ void prep_kernel(const float* __restrict__ w, const float* __restrict__ wf) {
    int t = threadIdx.x;
    if (t < NPM * 9) {
        int n = t / 9;
        float wv = fminf(fmaxf(w[t], -1.f), 1.f);
        float f  = fminf(fmaxf(wf[n], 1.f), 255.f);
        g_w[t] = wv * f;
    }
    if (t < NPM) g_maxbits[t] = 0u;
}

// Load one image row segment cols [w0-1 .. w0+4] (zero-padded) from GMEM,
// duplicated into f32x2 broadcast pairs. (Kernel A path — unchanged from R5.)
__device__ __forceinline__ void load_row_dup(const float* __restrict__ img, int r, int w0,
                                             bool hl, bool hr, u64 d[6]) {
    if ((unsigned)r < (unsigned)IMGSZ) {
        const float4 m = *reinterpret_cast<const float4*>(img + (r << 6) + w0);
        d[0] = dup2(hl ? img[(r << 6) + w0 - 1] : 0.f);
        d[1] = dup2(m.x); d[2] = dup2(m.y); d[3] = dup2(m.z); d[4] = dup2(m.w);
        d[5] = dup2(hr ? img[(r << 6) + w0 + 4] : 0.f);
    } else {
#pragma unroll
        for (int j = 0; j < 6; j++) d[j] = 0ull;
    }
}

// Same, but sourced from the SMEM-staged image (kernel C path).
__device__ __forceinline__ void load_row_dup_s(const float* __restrict__ simg, int r, int w0,
                                               bool hl, bool hr, u64 d[6]) {
    if ((unsigned)r < (unsigned)IMGSZ) {
        const float4 m = *reinterpret_cast<const float4*>(simg + (r << 6) + w0);
        d[0] = dup2(hl ? simg[(r << 6) + w0 - 1] : 0.f);
        d[1] = dup2(m.x); d[2] = dup2(m.y); d[3] = dup2(m.z); d[4] = dup2(m.w);
        d[5] = dup2(hr ? simg[(r << 6) + w0 + 4] : 0.f);
    } else {
#pragma unroll
        for (int j = 0; j < 6; j++) d[j] = 0ull;
    }
}

// 9-tap packed conv for one output pixel, multiplier-pair p. Fixed tap order
// -> bit-exact across all variants.
__device__ __forceinline__ u64 conv9(const u64* wp, const u64 r0[6], const u64 r1[6],
                                     const u64 r2[6], int oc) {
    u64 a = mul2(wp[0], r0[oc]);
    a = fma2(wp[1], r0[oc + 1], a);
    a = fma2(wp[2], r0[oc + 2], a);
    a = fma2(wp[3], r1[oc],     a);
    a = fma2(wp[4], r1[oc + 1], a);
    a = fma2(wp[5], r1[oc + 2], a);
    a = fma2(wp[6], r2[oc],     a);
    a = fma2(wp[7], r2[oc + 1], a);
    a = fma2(wp[8], r2[oc + 2], a);
    return a;
}

// ---------------------------------------------------------------------------
// Kernel A: conv (4 kernels x all channels) + global max per multiplier index.
// One block per channel, 256 threads, 4x4 px per thread. (R5 form, unchanged.)
// ---------------------------------------------------------------------------
__global__ void __launch_bounds__(256)
conv_max_kernel(const float* __restrict__ in) {
    int c = blockIdx.x;
    const float* img = in + c * (IMGSZ * IMGSZ);
    int tid = threadIdx.x;
    int tx = tid & 15, ty = tid >> 4;
    int w0 = tx << 2, r0 = ty << 2;
    bool hl = (tx != 0), hr = (tx != 15);

    u64 wp[2][9];
#pragma unroll
    for (int p = 0; p < 2; p++)
#pragma unroll
        for (int j = 0; j < 9; j++)
            wp[p][j] = pack2(g_w[(2 * p) * 9 + j], g_w[(2 * p + 1) * 9 + j]);

    u64 rw[3][6];
    load_row_dup(img, r0 - 1, w0, hl, hr, rw[0]);
    load_row_dup(img, r0,     w0, hl, hr, rw[1]);

    const float NEG_INF = __int_as_float(0xff800000);
    float mx[4] = {NEG_INF, NEG_INF, NEG_INF, NEG_INF};

#pragma unroll
    for (int orr = 0; orr < 4; orr++) {
        load_row_dup(img, r0 + orr + 1, w0, hl, hr, rw[2]);
#pragma unroll
        for (int p = 0; p < 2; p++) {
#pragma unroll
            for (int oc = 0; oc < 4; oc++) {
                u64 a = conv9(wp[p], rw[0], rw[1], rw[2], oc);
                float f0, f1; unpack2(a, f0, f1);
                mx[2 * p]     = fmaxf(mx[2 * p],     f0);
                mx[2 * p + 1] = fmaxf(mx[2 * p + 1], f1);
            }
        }
#pragma unroll
        for (int j = 0; j < 6; j++) { rw[0][j] = rw[1][j]; rw[1][j] = rw[2][j]; }
    }

#pragma unroll
    for (int n = 0; n < 4; n++) {
#pragma unroll
        for (int off = 16; off; off >>= 1)
            mx[n] = fmaxf(mx[n], __shfl_xor_sync(0xffffffffu, mx[n], off));
    }

    __shared__ float red[8][4];
    int wid = tid >> 5, lane = tid & 31;
    if (lane == 0) {
        red[wid][0] = mx[0]; red[wid][1] = mx[1];
        red[wid][2] = mx[2]; red[wid][3] = mx[3];
    }
    __syncthreads();
    if (tid < 4) {
        float m = red[0][tid];
#pragma unroll
        for (int wi = 1; wi < 8; wi++) m = fmaxf(m, red[wi][tid]);
        atomicMax(&g_maxbits[tid], fkey(m));
    }
}

// ---------------------------------------------------------------------------
// Kernel C: SMEM-staged image. One coalesced cooperative load per block
// (high-MLP LDG.128), then the conv window comes from 29-cycle LDS instead
// of 234-577 cycle gathered LDGs. No rolling row buffer (rows re-read from
// smem per output row) -> fewer long-lived registers.
// ---------------------------------------------------------------------------
__global__ void __launch_bounds__(256)
conv_out_kernel(const float* __restrict__ in, float* __restrict__ out) {
    __shared__ float simg[IMGSZ * IMGSZ];   // 16 KB
    int c = blockIdx.x;
    const float* img = in + c * (IMGSZ * IMGSZ);
    int tid = threadIdx.x;

    // Cooperative coalesced load: 4 independent LDG.128 per thread.
    {
        const float4* src = reinterpret_cast<const float4*>(img);
        float4* dst = reinterpret_cast<float4*>(simg);
#pragma unroll
        for (int i = 0; i < 4; i++)
            dst[tid + i * 256] = src[tid + i * 256];
    }

    u64 wp[2][9];
#pragma unroll
    for (int p = 0; p < 2; p++)
#pragma unroll
        for (int j = 0; j < 9; j++)
            wp[p][j] = pack2(g_w[(2 * p) * 9 + j], g_w[(2 * p + 1) * 9 + j]);

    u64 scp[2];
    {
        float sc[4];
#pragma unroll
        for (int n = 0; n < 4; n++) {
            float m   = keyf(g_maxbits[n]);
            float div = m * 0.0078125f;   // /128
            float s = 1.f;
            if (div > 0.f) s = exp2f(-rintf(log2f(div)));   // round-half-even == jnp.round
            sc[n] = s;
        }
        scp[0] = pack2(sc[0], sc[1]);
        scp[1] = pack2(sc[2], sc[3]);
    }

    __syncthreads();

    int tx = tid & 15, ty = tid >> 4;
    int w0 = tx << 2, r0 = ty << 2;
    bool hl = (tx != 0), hr = (tx != 15);

    float* outc = out + c * (IMGSZ * IMGSZ) + w0;

#pragma unroll
    for (int orr = 0; orr < 4; orr++) {
        int r = r0 + orr;
        u64 rw0[6], rw1[6], rw2[6];
        load_row_dup_s(simg, r - 1, w0, hl, hr, rw0);
        load_row_dup_s(simg, r,     w0, hl, hr, rw1);
        load_row_dup_s(simg, r + 1, w0, hl, hr, rw2);

        int rowoff = r << 6;
        float4 o0, o1, o2, o3;
#pragma unroll
        for (int oc = 0; oc < 4; oc++) {
            u64 a0 = conv9(wp[0], rw0, rw1, rw2, oc);
            u64 r0p = fma2(a0, scp[0], rw1[oc + 1]);   // input + conv*scale (n0,n1)
            float f0, f1; unpack2(r0p, f0, f1);
            ((float*)&o0)[oc] = f0;
            ((float*)&o1)[oc] = f1;

            u64 a1 = conv9(wp[1], rw0, rw1, rw2, oc);
            u64 r1p = fma2(a1, scp[1], rw1[oc + 1]);   // (n2,n3)
            float f2, f3; unpack2(r1p, f2, f3);
            ((float*)&o2)[oc] = f2;
            ((float*)&o3)[oc] = f3;
        }
        *reinterpret_cast<float4*>(outc + 0 * OUT_N + rowoff) = o0;
        *reinterpret_cast<float4*>(outc + 1 * OUT_N + rowoff) = o1;
        *reinterpret_cast<float4*>(outc + 2 * OUT_N + rowoff) = o2;
        *reinterpret_cast<float4*>(outc + 3 * OUT_N + rowoff) = o3;
    }
}

// ---------------------------------------------------------------------------
extern "C" void kernel_launch(void* const* d_in, const int* in_sizes, int n_in,
                              void* d_out, int out_size) {
    const float* input  = (const float*)d_in[0];   // [1,4096,64,64]
    const float* weight = (const float*)d_in[1];   // [4,9]
    const float* wf     = (const float*)d_in[2];   // [4,1]
    float* out = (float*)d_out;                    // [4,1,4096,64,64]

    prep_kernel<<<1, 64>>>(weight, wf);
    conv_max_kernel<<<C_CH, 256>>>(input);
    conv_out_kernel<<<C_CH, 256>>>(input, out);
}